// round 6
// baseline (speedup 1.0000x reference)
#include <cuda_runtime.h>
#include <cuda_bf16.h>
#include <math.h>
#include <stdint.h>

typedef __nv_bfloat16 bf16;

#define BSZ 64
#define NN  256
#define CC  512
#define NC  (NN*CC)     // 131072
#define NNN (NN*NN)     // 65536
#define WSZ (CC*CC)     // 262144

// ---- bf16 hi/lo packed operands & intermediates (no cudaMalloc allowed) ----
__device__ __align__(256) bf16 g_fh[BSZ*NC],  g_fl[BSZ*NC];
__device__ __align__(256) bf16 g_ajh[BSZ*NNN], g_ajl[BSZ*NNN];
__device__ __align__(256) bf16 g_wh[11*WSZ],  g_wl[11*WSZ];
__device__ __align__(256) bf16 g_b1h[BSZ*NC], g_b1l[BSZ*NC];
__device__ __align__(256) bf16 g_b2h[BSZ*NC], g_b2l[BSZ*NC];
__device__ __align__(256) bf16 g_b3h[BSZ*NC], g_b3l[BSZ*NC];
__device__ __align__(256) bf16 g_b4h[BSZ*NC], g_b4l[BSZ*NC];
__device__ __align__(256) bf16 g_Sh[BSZ*NNN], g_Sl[BSZ*NNN];

#define STG        32768
#define SMEM_TOTAL (2*STG)   // 2-stage -> 64KB -> 2 CTAs/SM

__device__ __forceinline__ uint32_t smem_u32(const void* p) {
    uint32_t a;
    asm("{ .reg .u64 t; cvta.to.shared.u64 t, %1; cvt.u32.u64 %0, t; }" : "=r"(a) : "l"(p));
    return a;
}
// [row][k] bf16 layout, rows of 64B, swizzled
__device__ __forceinline__ uint32_t off_rk(uint32_t r, uint32_t cb) {
    return r * 64u + ((((cb >> 4) ^ ((r >> 1) & 3u)) & 3u) << 4) + (cb & 15u);
}
// [k][col] bf16 layout, rows of 256B, swizzled
__device__ __forceinline__ uint32_t off_kn(uint32_t k, uint32_t cb) {
    uint32_t ch = (cb >> 4) ^ (k & 7u);
    return k * 256u + ((ch & 15u) << 4) + (cb & 15u);
}
__device__ __forceinline__ void ldsm4(uint32_t& r0, uint32_t& r1, uint32_t& r2, uint32_t& r3, uint32_t a) {
    asm volatile("ldmatrix.sync.aligned.m8n8.x4.shared.b16 {%0,%1,%2,%3}, [%4];"
                 : "=r"(r0), "=r"(r1), "=r"(r2), "=r"(r3) : "r"(a));
}
__device__ __forceinline__ void ldsm4t(uint32_t& r0, uint32_t& r1, uint32_t& r2, uint32_t& r3, uint32_t a) {
    asm volatile("ldmatrix.sync.aligned.m8n8.x4.trans.shared.b16 {%0,%1,%2,%3}, [%4];"
                 : "=r"(r0), "=r"(r1), "=r"(r2), "=r"(r3) : "r"(a));
}
__device__ __forceinline__ void mma16816(float* c, const uint32_t* a, const uint32_t* b) {
    asm volatile(
        "mma.sync.aligned.m16n8k16.row.col.f32.bf16.bf16.f32 "
        "{%0,%1,%2,%3}, {%4,%5,%6,%7}, {%8,%9}, {%0,%1,%2,%3};"
        : "+f"(c[0]), "+f"(c[1]), "+f"(c[2]), "+f"(c[3])
        : "r"(a[0]), "r"(a[1]), "r"(a[2]), "r"(a[3]), "r"(b[0]), "r"(b[1]));
}

// Stage one 128x32 bf16 tile pair (hi at dsthi, lo at dsthi+8192): plain LDG+STS.
template<int T>
__device__ __forceinline__ void stage(const bf16* __restrict__ sh,
                                      const bf16* __restrict__ sl,
                                      int ld, int k0, int r0,
                                      char* dsthi, int tid) {
    #pragma unroll
    for (int it = 0; it < 2; it++) {
        int g = it * 256 + tid;
        long sb; uint32_t off;
        if (T == 0) {
            int r = g >> 2; uint32_t cb = (uint32_t)(g & 3) * 16;
            off = off_rk((uint32_t)r, cb);
            sb = ((long)(r0 + r) * ld + k0) * 2 + cb;
        } else {
            int kr = g >> 4; uint32_t cb = (uint32_t)(g & 15) * 16;
            off = off_kn((uint32_t)kr, cb);
            sb = ((long)(k0 + kr) * ld + r0) * 2 + cb;
        }
        uint4 vh = *(const uint4*)((const char*)sh + sb);
        uint4 vl = *(const uint4*)((const char*)sl + sb);
        *(uint4*)(dsthi + off)        = vh;
        *(uint4*)(dsthi + 8192 + off) = vl;
    }
}

// ---------------------------------------------------------------------------
// bf16x2-split (3-product) tensor-core GEMM on prepacked hi/lo operands.
//   TA=1: A[m][k]=src[k*lda+m] (adj^T). TB=1: B[n][k]=src[k*ldb+n].
//   EPI: 0 store pair | 1 relu pair | 2 relu + old pair | 3 relu + Add -> fp32
//   PAIR=1: gridDim.x doubled; upper half uses (B2, D0b/D1b).
// CTA 128x128, BK=32, 256 thr, warp tile 32x64; 2-stage LDG/STS pipeline.
// ---------------------------------------------------------------------------
template<int TA, int TB, int EPI, int PAIR>
__global__ __launch_bounds__(256)
void tc_gemm(const bf16* __restrict__ Ah_, const bf16* __restrict__ Al_, long sA, int lda,
             const bf16* __restrict__ Bh_, const bf16* __restrict__ Bl_, long sB, int ldb,
             void* __restrict__ C0, void* __restrict__ C1, long sC, int ldc,
             const bf16* __restrict__ Adh_, const bf16* __restrict__ Adl_, long sAdd, int K,
             const bf16* __restrict__ B2h_, const bf16* __restrict__ B2l_,
             void* __restrict__ D0b, void* __restrict__ D1b)
{
    extern __shared__ char smem[];
    const uint32_t sbase = smem_u32(smem);
    const int tid = threadIdx.x, lane = tid & 31, wid = tid >> 5;
    const int b  = blockIdx.z;

    int bx = blockIdx.x;
    const bf16* Bhs = Bh_; const bf16* Bls = Bl_;
    void* C0s = C0; void* C1s = C1;
    if (PAIR) {
        int half = gridDim.x >> 1;
        if (bx >= half) { bx -= half; Bhs = B2h_; Bls = B2l_; C0s = D0b; C1s = D1b; }
    }
    const int m0 = blockIdx.y * 128;
    const int n0 = bx * 128;

    const bf16* Ahp = Ah_ + (long)b * sA;
    const bf16* Alp = Al_ + (long)b * sA;
    const bf16* Bhp = Bhs + (long)b * sB;
    const bf16* Blp = Bls + (long)b * sB;

    const int am = (wid & 3) * 32;
    const int bn = (wid >> 2) * 64;

    float acc[2][8][4];
    #pragma unroll
    for (int i = 0; i < 2; i++)
        #pragma unroll
        for (int j = 0; j < 8; j++)
            #pragma unroll
            for (int e = 0; e < 4; e++) acc[i][j][e] = 0.f;

    const int nch = K >> 5;

    stage<TA>(Ahp, Alp, lda, 0, m0, smem,         tid);
    stage<TB>(Bhp, Blp, ldb, 0, n0, smem + 16384, tid);
    __syncthreads();

    for (int ch = 0; ch < nch; ch++) {
        const int d = ch & 1;
        if (ch + 1 < nch) {
            char* nxt = smem + (uint32_t)(d ^ 1) * STG;
            stage<TA>(Ahp, Alp, lda, (ch + 1) << 5, m0, nxt,         tid);
            stage<TB>(Bhp, Blp, ldb, (ch + 1) << 5, n0, nxt + 16384, tid);
        }
        const uint32_t uAh = sbase + (uint32_t)d * STG;
        const uint32_t uAl = uAh + 8192;
        const uint32_t uBh = uAh + 16384;
        const uint32_t uBl = uAh + 24576;

        #pragma unroll
        for (int ks = 0; ks < 2; ks++) {
            uint32_t Afh[2][4], Afl[2][4];
            #pragma unroll
            for (int mt = 0; mt < 2; mt++) {
                uint32_t off;
                if (!TA) {
                    uint32_t row = (uint32_t)(am + mt * 16 + (lane & 15));
                    uint32_t cb  = (uint32_t)(ks * 32 + ((lane >> 4) << 4));
                    off = off_rk(row, cb);
                } else {
                    uint32_t grp = lane >> 3, t8 = lane & 7;
                    uint32_t k   = (uint32_t)(ks * 16) + ((grp >> 1) << 3) + t8;
                    uint32_t cb  = (uint32_t)(am + mt * 16 + ((grp & 1) << 3)) * 2;
                    off = off_kn(k, cb);
                }
                if (!TA) {
                    ldsm4(Afh[mt][0], Afh[mt][1], Afh[mt][2], Afh[mt][3], uAh + off);
                    ldsm4(Afl[mt][0], Afl[mt][1], Afl[mt][2], Afl[mt][3], uAl + off);
                } else {
                    ldsm4t(Afh[mt][0], Afh[mt][1], Afh[mt][2], Afh[mt][3], uAh + off);
                    ldsm4t(Afl[mt][0], Afl[mt][1], Afl[mt][2], Afl[mt][3], uAl + off);
                }
            }
            uint32_t Bfh[8][2], Bfl[8][2];
            #pragma unroll
            for (int p = 0; p < 4; p++) {
                uint32_t off;
                if (!TB) {
                    uint32_t row = (uint32_t)(bn + p * 16 + (lane & 15));
                    uint32_t cb  = (uint32_t)(ks * 32 + ((lane >> 4) << 4));
                    off = off_rk(row, cb);
                } else {
                    uint32_t grp = lane >> 3, t8 = lane & 7;
                    uint32_t k   = (uint32_t)(ks * 16) + ((grp >> 1) << 3) + t8;
                    uint32_t cb  = (uint32_t)(bn + p * 16 + ((grp & 1) << 3)) * 2;
                    off = off_kn(k, cb);
                }
                uint32_t r0, r1, r2, r3;
                if (!TB) ldsm4 (r0, r1, r2, r3, uBh + off);
                else     ldsm4t(r0, r1, r2, r3, uBh + off);
                Bfh[2*p][0] = r0; Bfh[2*p][1] = r2; Bfh[2*p+1][0] = r1; Bfh[2*p+1][1] = r3;
                if (!TB) ldsm4 (r0, r1, r2, r3, uBl + off);
                else     ldsm4t(r0, r1, r2, r3, uBl + off);
                Bfl[2*p][0] = r0; Bfl[2*p][1] = r2; Bfl[2*p+1][0] = r1; Bfl[2*p+1][1] = r3;
            }
            // 3 products, reordered for accumulator ILP (per-acc order HH,HL,LH preserved)
            #pragma unroll
            for (int mt = 0; mt < 2; mt++)
                #pragma unroll
                for (int nt = 0; nt < 8; nt++) mma16816(acc[mt][nt], Afh[mt], Bfh[nt]);
            #pragma unroll
            for (int mt = 0; mt < 2; mt++)
                #pragma unroll
                for (int nt = 0; nt < 8; nt++) mma16816(acc[mt][nt], Afh[mt], Bfl[nt]);
            #pragma unroll
            for (int mt = 0; mt < 2; mt++)
                #pragma unroll
                for (int nt = 0; nt < 8; nt++) mma16816(acc[mt][nt], Afl[mt], Bfh[nt]);
        }
        __syncthreads();
    }

    // ---- epilogue ----
    #pragma unroll
    for (int mt = 0; mt < 2; mt++) {
        #pragma unroll
        for (int half = 0; half < 2; half++) {
            int row = m0 + am + mt * 16 + (lane >> 2) + half * 8;
            long base = (long)b * sC + (long)row * ldc + n0 + bn + (lane & 3) * 2;
            long abase = (EPI == 3)
                ? (long)b * sAdd + (long)row * ldc + n0 + bn + (lane & 3) * 2 : 0;
            #pragma unroll
            for (int nt = 0; nt < 8; nt++) {
                float x = acc[mt][nt][half * 2 + 0];
                float y = acc[mt][nt][half * 2 + 1];
                if (EPI >= 1) { x = fmaxf(x, 0.f); y = fmaxf(y, 0.f); }
                if (EPI == 2) {
                    __nv_bfloat162 oh = *(const __nv_bfloat162*)((const bf16*)C0s + base + nt * 8);
                    __nv_bfloat162 ol = *(const __nv_bfloat162*)((const bf16*)C1s + base + nt * 8);
                    x += __bfloat162float(oh.x) + __bfloat162float(ol.x);
                    y += __bfloat162float(oh.y) + __bfloat162float(ol.y);
                }
                if (EPI == 3) {
                    __nv_bfloat162 oh = *(const __nv_bfloat162*)(Adh_ + abase + nt * 8);
                    __nv_bfloat162 ol = *(const __nv_bfloat162*)(Adl_ + abase + nt * 8);
                    x += __bfloat162float(oh.x) + __bfloat162float(ol.x);
                    y += __bfloat162float(oh.y) + __bfloat162float(ol.y);
                    float2 v; v.x = x; v.y = y;
                    *(float2*)((float*)C0s + base + nt * 8) = v;
                } else {
                    __nv_bfloat162 hv, lv;
                    hv.x = __float2bfloat16_rn(x);
                    lv.x = __float2bfloat16_rn(x - __bfloat162float(hv.x));
                    hv.y = __float2bfloat16_rn(y);
                    lv.y = __float2bfloat16_rn(y - __bfloat162float(hv.y));
                    *(__nv_bfloat162*)((bf16*)C0s + base + nt * 8) = hv;
                    *(__nv_bfloat162*)((bf16*)C1s + base + nt * 8) = lv;
                }
            }
        }
    }
}

// ---------------------------------------------------------------------------
// Row softmax over last dim (256) on bf16 hi/lo pairs, in place.
// ---------------------------------------------------------------------------
__global__ __launch_bounds__(256)
void softmax_kernel(bf16* __restrict__ Ph, bf16* __restrict__ Pl)
{
    __shared__ float sm[8];
    const long row = blockIdx.x;
    bf16* ph = Ph + row * (long)NN;
    bf16* pl = Pl + row * (long)NN;
    const int t = threadIdx.x;

    float v = __bfloat162float(ph[t]) + __bfloat162float(pl[t]);
    float m = v;
    #pragma unroll
    for (int o = 16; o > 0; o >>= 1) m = fmaxf(m, __shfl_xor_sync(0xffffffffu, m, o));
    if ((t & 31) == 0) sm[t >> 5] = m;
    __syncthreads();
    m = sm[0];
    #pragma unroll
    for (int i = 1; i < 8; i++) m = fmaxf(m, sm[i]);

    float e = expf(v - m);
    float s = e;
    #pragma unroll
    for (int o = 16; o > 0; o >>= 1) s += __shfl_xor_sync(0xffffffffu, s, o);
    __syncthreads();
    if ((t & 31) == 0) sm[t >> 5] = s;
    __syncthreads();
    s = 0.f;
    #pragma unroll
    for (int i = 0; i < 8; i++) s += sm[i];

    float r = e / s;
    bf16 hb = __float2bfloat16_rn(r);
    ph[t] = hb;
    pl[t] = __float2bfloat16_rn(r - __bfloat162float(hb));
}

// ---------------------------------------------------------------------------
// Pack fp32 -> bf16 hi/lo
// ---------------------------------------------------------------------------
__global__ __launch_bounds__(256)
void pack2(const float4* __restrict__ src, bf16* __restrict__ dh, bf16* __restrict__ dl, int n4)
{
    int i = blockIdx.x * 256 + threadIdx.x;
    if (i >= n4) return;
    float4 v = src[i];
    float a[4] = {v.x, v.y, v.z, v.w};
    bf16 hb[4], lb[4];
    #pragma unroll
    for (int e = 0; e < 4; e++) {
        hb[e] = __float2bfloat16_rn(a[e]);
        lb[e] = __float2bfloat16_rn(a[e] - __bfloat162float(hb[e]));
    }
    __nv_bfloat162 h0, h1, l0, l1;
    h0.x = hb[0]; h0.y = hb[1]; h1.x = hb[2]; h1.y = hb[3];
    l0.x = lb[0]; l0.y = lb[1]; l1.x = lb[2]; l1.y = lb[3];
    ((__nv_bfloat162*)dh)[2*i]   = h0; ((__nv_bfloat162*)dh)[2*i+1] = h1;
    ((__nv_bfloat162*)dl)[2*i]   = l0; ((__nv_bfloat162*)dl)[2*i+1] = l1;
}

__global__ __launch_bounds__(256)
void pack_w(const float* s0, const float* s1, const float* s2, const float* s3,
            const float* s4, const float* s5, const float* s6, const float* s7,
            const float* s8, const float* s9, const float* s10,
            bf16* __restrict__ dh, bf16* __restrict__ dl)
{
    long i4 = (long)blockIdx.x * 256 + threadIdx.x;
    long idx = i4 * 4;
    int which = (int)(idx >> 18);
    long off  = idx & (WSZ - 1);
    const float* s;
    switch (which) {
        case 0: s = s0; break;  case 1: s = s1; break;  case 2: s = s2; break;
        case 3: s = s3; break;  case 4: s = s4; break;  case 5: s = s5; break;
        case 6: s = s6; break;  case 7: s = s7; break;  case 8: s = s8; break;
        case 9: s = s9; break;  default: s = s10; break;
    }
    float4 v = *(const float4*)(s + off);
    float a[4] = {v.x, v.y, v.z, v.w};
    bf16 hb[4], lb[4];
    #pragma unroll
    for (int e = 0; e < 4; e++) {
        hb[e] = __float2bfloat16_rn(a[e]);
        lb[e] = __float2bfloat16_rn(a[e] - __bfloat162float(hb[e]));
    }
    __nv_bfloat162 h0, h1, l0, l1;
    h0.x = hb[0]; h0.y = hb[1]; h1.x = hb[2]; h1.y = hb[3];
    l0.x = lb[0]; l0.y = lb[1]; l1.x = lb[2]; l1.y = lb[3];
    *(__nv_bfloat162*)(dh + idx)     = h0; *(__nv_bfloat162*)(dh + idx + 2) = h1;
    *(__nv_bfloat162*)(dl + idx)     = l0; *(__nv_bfloat162*)(dl + idx + 2) = l1;
}

// ---------------------------------------------------------------------------
extern "C" void kernel_launch(void* const* d_in, const int* in_sizes, int n_in,
                              void* d_out, int out_size)
{
    const float* f   = (const float*)d_in[0];
    const float* adj = (const float*)d_in[2];
    const float* W[11] = {
        (const float*)d_in[3],  (const float*)d_in[4],
        (const float*)d_in[5],  (const float*)d_in[8],
        (const float*)d_in[6],  (const float*)d_in[9],
        (const float*)d_in[7],  (const float*)d_in[10],
        (const float*)d_in[11], (const float*)d_in[12],
        (const float*)d_in[13]
    };
    float* out = (float*)d_out;

    bf16 *fh, *fl, *ajh, *ajl, *wh, *wl;
    bf16 *b1h, *b1l, *b2h, *b2l, *b3h, *b3l, *b4h, *b4l, *Sh, *Sl;
    cudaGetSymbolAddress((void**)&fh,  g_fh);  cudaGetSymbolAddress((void**)&fl,  g_fl);
    cudaGetSymbolAddress((void**)&ajh, g_ajh); cudaGetSymbolAddress((void**)&ajl, g_ajl);
    cudaGetSymbolAddress((void**)&wh,  g_wh);  cudaGetSymbolAddress((void**)&wl,  g_wl);
    cudaGetSymbolAddress((void**)&b1h, g_b1h); cudaGetSymbolAddress((void**)&b1l, g_b1l);
    cudaGetSymbolAddress((void**)&b2h, g_b2h); cudaGetSymbolAddress((void**)&b2l, g_b2l);
    cudaGetSymbolAddress((void**)&b3h, g_b3h); cudaGetSymbolAddress((void**)&b3l, g_b3l);
    cudaGetSymbolAddress((void**)&b4h, g_b4h); cudaGetSymbolAddress((void**)&b4l, g_b4l);
    cudaGetSymbolAddress((void**)&Sh,  g_Sh);  cudaGetSymbolAddress((void**)&Sl,  g_Sl);

    cudaFuncSetAttribute(tc_gemm<0,0,0,1>, cudaFuncAttributeMaxDynamicSharedMemorySize, SMEM_TOTAL);
    cudaFuncSetAttribute(tc_gemm<0,0,0,0>, cudaFuncAttributeMaxDynamicSharedMemorySize, SMEM_TOTAL);
    cudaFuncSetAttribute(tc_gemm<0,1,0,1>, cudaFuncAttributeMaxDynamicSharedMemorySize, SMEM_TOTAL);
    cudaFuncSetAttribute(tc_gemm<0,1,0,0>, cudaFuncAttributeMaxDynamicSharedMemorySize, SMEM_TOTAL);
    cudaFuncSetAttribute(tc_gemm<0,1,1,0>, cudaFuncAttributeMaxDynamicSharedMemorySize, SMEM_TOTAL);
    cudaFuncSetAttribute(tc_gemm<1,1,2,0>, cudaFuncAttributeMaxDynamicSharedMemorySize, SMEM_TOTAL);
    cudaFuncSetAttribute(tc_gemm<0,1,3,0>, cudaFuncAttributeMaxDynamicSharedMemorySize, SMEM_TOTAL);

    // ---- pack ----
    pack2<<<BSZ*NC/4/256,  256>>>((const float4*)f,   fh,  fl,  BSZ*NC/4);
    pack2<<<BSZ*NNN/4/256, 256>>>((const float4*)adj, ajh, ajl, BSZ*NNN/4);
    pack_w<<<11*WSZ/4/256, 256>>>(W[0], W[1], W[2], W[3], W[4], W[5], W[6], W[7],
                                  W[8], W[9], W[10], wh, wl);

    #define WH(i) (wh + (long)(i)*WSZ)
    #define WL(i) (wl + (long)(i)*WSZ)
    const dim3 blk(256);
    const dim3 gP(2*CC/128, NN/128, BSZ);  // paired weight muls: (8,2,64)
    const dim3 g1(CC/128, NN/128, BSZ);    // (4,2,64)
    const dim3 g3(NN/128, NN/128, BSZ);    // (2,2,64)
    const int SM = SMEM_TOTAL;

    // similarity graph: b1 = f@Wse1^T, b2 = f@Wse2^T (paired), S = softmax(b1@b2^T)
    tc_gemm<0,0,0,1><<<gP, blk, SM>>>(fh, fl, NC, CC, WH(0), WL(0), 0, CC, b1h, b1l, NC, CC,
                                      0, 0, 0, CC, WH(1), WL(1), b2h, b2l);
    tc_gemm<0,0,0,0><<<g3, blk, SM>>>(b1h, b1l, NC, CC, b2h, b2l, NC, CC, Sh, Sl, NNN, NN,
                                      0, 0, 0, CC, 0, 0, 0, 0);
    softmax_kernel<<<BSZ*NN, blk>>>(Sh, Sl);

    // st layer 1: b3 = f@Wst1, b4 = f@Wst1b (paired); b1 = relu(adj@b3); b1 += relu(adjT@b4)
    tc_gemm<0,1,0,1><<<gP, blk, SM>>>(fh, fl, NC, CC, WH(2), WL(2), 0, CC, b3h, b3l, NC, CC,
                                      0, 0, 0, CC, WH(3), WL(3), b4h, b4l);
    tc_gemm<0,1,1,0><<<g1, blk, SM>>>(ajh, ajl, NNN, NN, b3h, b3l, NC, CC, b1h, b1l, NC, CC,
                                      0, 0, 0, NN, 0, 0, 0, 0);
    tc_gemm<1,1,2,0><<<g1, blk, SM>>>(ajh, ajl, NNN, NN, b4h, b4l, NC, CC, b1h, b1l, NC, CC,
                                      0, 0, 0, NN, 0, 0, 0, 0);
    // st layer 2
    tc_gemm<0,1,0,1><<<gP, blk, SM>>>(b1h, b1l, NC, CC, WH(4), WL(4), 0, CC, b3h, b3l, NC, CC,
                                      0, 0, 0, CC, WH(5), WL(5), b4h, b4l);
    tc_gemm<0,1,1,0><<<g1, blk, SM>>>(ajh, ajl, NNN, NN, b3h, b3l, NC, CC, b2h, b2l, NC, CC,
                                      0, 0, 0, NN, 0, 0, 0, 0);
    tc_gemm<1,1,2,0><<<g1, blk, SM>>>(ajh, ajl, NNN, NN, b4h, b4l, NC, CC, b2h, b2l, NC, CC,
                                      0, 0, 0, NN, 0, 0, 0, 0);
    // st layer 3
    tc_gemm<0,1,0,1><<<gP, blk, SM>>>(b2h, b2l, NC, CC, WH(6), WL(6), 0, CC, b3h, b3l, NC, CC,
                                      0, 0, 0, CC, WH(7), WL(7), b4h, b4l);
    tc_gemm<0,1,1,0><<<g1, blk, SM>>>(ajh, ajl, NNN, NN, b3h, b3l, NC, CC, b1h, b1l, NC, CC,
                                      0, 0, 0, NN, 0, 0, 0, 0);
    tc_gemm<1,1,2,0><<<g1, blk, SM>>>(ajh, ajl, NNN, NN, b4h, b4l, NC, CC, b1h, b1l, NC, CC,
                                      0, 0, 0, NN, 0, 0, 0, 0);

    // sim branch
    tc_gemm<0,1,0,0><<<g1, blk, SM>>>(fh, fl, NC, CC, WH(8), WL(8), 0, CC, b3h, b3l, NC, CC,
                                      0, 0, 0, CC, 0, 0, 0, 0);
    tc_gemm<0,1,1,0><<<g1, blk, SM>>>(Sh, Sl, NNN, NN, b3h, b3l, NC, CC, b2h, b2l, NC, CC,
                                      0, 0, 0, NN, 0, 0, 0, 0);
    tc_gemm<0,1,0,0><<<g1, blk, SM>>>(b2h, b2l, NC, CC, WH(9), WL(9), 0, CC, b3h, b3l, NC, CC,
                                      0, 0, 0, CC, 0, 0, 0, 0);
    tc_gemm<0,1,1,0><<<g1, blk, SM>>>(Sh, Sl, NNN, NN, b3h, b3l, NC, CC, b4h, b4l, NC, CC,
                                      0, 0, 0, NN, 0, 0, 0, 0);
    tc_gemm<0,1,0,0><<<g1, blk, SM>>>(b4h, b4l, NC, CC, WH(10), WL(10), 0, CC, b3h, b3l, NC, CC,
                                      0, 0, 0, CC, 0, 0, 0, 0);
    // out = relu(S @ b3) + b1  (fp32 out)
    tc_gemm<0,1,3,0><<<g1, blk, SM>>>(Sh, Sl, NNN, NN, b3h, b3l, NC, CC, out, nullptr, NC, CC,
                                      b1h, b1l, NC, NN, 0, 0, 0, 0);
}

// round 7
// speedup vs baseline: 1.7878x; 1.7878x over previous
#include <cuda_runtime.h>
#include <cuda_bf16.h>
#include <math.h>
#include <stdint.h>

#define BSZ 64
#define NN  256
#define CC  512
#define NC  (NN*CC)     // 131072
#define NNN (NN*NN)     // 65536

// Scratch (no cudaMalloc allowed)
__device__ float g_b1[BSZ*NC];
__device__ float g_b2[BSZ*NC];
__device__ float g_b3[BSZ*NC];
__device__ float g_b4[BSZ*NC];
__device__ float g_S [BSZ*NNN];

// SMEM stage layout: Ah @0 (8KB) | Al @8K | Bh @16K | Bl @24K ; two stages.
#define STG        32768
#define SMEM_TOTAL (2*STG)

__device__ __forceinline__ uint32_t smem_u32(const void* p) {
    uint32_t a;
    asm("{ .reg .u64 t; cvta.to.shared.u64 t, %1; cvt.u32.u64 %0, t; }" : "=r"(a) : "l"(p));
    return a;
}

// [row][k] layout, 128 rows x 64B; swizzle keeps ldmatrix phases conflict-free
__device__ __forceinline__ uint32_t off_rk(uint32_t r, uint32_t cb) {
    return r * 64u + ((((cb >> 4) ^ ((r >> 1) & 3u)) & 3u) << 4) + (cb & 15u);
}
// [k][col] layout, 32 rows x 256B
__device__ __forceinline__ uint32_t off_kn(uint32_t k, uint32_t cb) {
    uint32_t ch = (cb >> 4) ^ (k & 7u);
    return k * 256u + (ch << 4) + (cb & 15u);
}

__device__ __forceinline__ void ldsm4(uint32_t& r0, uint32_t& r1, uint32_t& r2, uint32_t& r3, uint32_t a) {
    asm volatile("ldmatrix.sync.aligned.m8n8.x4.shared.b16 {%0,%1,%2,%3}, [%4];"
                 : "=r"(r0), "=r"(r1), "=r"(r2), "=r"(r3) : "r"(a));
}
__device__ __forceinline__ void ldsm4t(uint32_t& r0, uint32_t& r1, uint32_t& r2, uint32_t& r3, uint32_t a) {
    asm volatile("ldmatrix.sync.aligned.m8n8.x4.trans.shared.b16 {%0,%1,%2,%3}, [%4];"
                 : "=r"(r0), "=r"(r1), "=r"(r2), "=r"(r3) : "r"(a));
}
__device__ __forceinline__ void mma16816(float* c, const uint32_t* a, const uint32_t* b) {
    asm volatile(
        "mma.sync.aligned.m16n8k16.row.col.f32.bf16.bf16.f32 "
        "{%0,%1,%2,%3}, {%4,%5,%6,%7}, {%8,%9}, {%0,%1,%2,%3};"
        : "+f"(c[0]), "+f"(c[1]), "+f"(c[2]), "+f"(c[3])
        : "r"(a[0]), "r"(a[1]), "r"(a[2]), "r"(a[3]), "r"(b[0]), "r"(b[1]));
}

// Convert 8 fp32 -> 8 bf16 hi + 8 bf16 lo, write 16B each.
__device__ __forceinline__ void cvt_store8(const float4 v0, const float4 v1,
                                           char* ph, char* pl) {
    float v[8] = {v0.x, v0.y, v0.z, v0.w, v1.x, v1.y, v1.z, v1.w};
    unsigned short hs[8], ls[8];
    #pragma unroll
    for (int e = 0; e < 8; e++) {
        __nv_bfloat16 hb = __float2bfloat16_rn(v[e]);
        float lf = v[e] - __bfloat162float(hb);
        __nv_bfloat16 lb = __float2bfloat16_rn(lf);
        hs[e] = *(unsigned short*)&hb;
        ls[e] = *(unsigned short*)&lb;
    }
    *(uint4*)ph = *(uint4*)hs;
    *(uint4*)pl = *(uint4*)ls;
}

// Stage one 128x32 operand tile (fp32 -> bf16 hi/lo split).
// T=0: source row-major rows=tile rows (m or n), ld over k.  layout [r][k].
// T=1: source row-major rows=k (transposed operand).          layout [k][c].
template<int T>
__device__ __forceinline__ void stage_tile(const float* __restrict__ src, int ld,
                                           int k0, int r0,
                                           char* sh, char* sl, int tid) {
    if (T == 0) {
        #pragma unroll
        for (int it = 0; it < 2; it++) {
            int idx = it * 256 + tid;
            int r = idx >> 2, cb8 = (idx & 3) * 8;
            const float* p = src + (long)(r0 + r) * ld + k0 + cb8;
            float4 a = *(const float4*)p;
            float4 b = *(const float4*)(p + 4);
            uint32_t off = off_rk((uint32_t)r, (uint32_t)cb8 * 2);
            cvt_store8(a, b, sh + off, sl + off);
        }
    } else {
        #pragma unroll
        for (int it = 0; it < 2; it++) {
            int idx = it * 256 + tid;
            int kr = idx >> 4, cb8 = (idx & 15) * 8;
            const float* p = src + (long)(k0 + kr) * ld + r0 + cb8;
            float4 a = *(const float4*)p;
            float4 b = *(const float4*)(p + 4);
            uint32_t off = off_kn((uint32_t)kr, (uint32_t)cb8 * 2);
            cvt_store8(a, b, sh + off, sl + off);
        }
    }
}

// ---------------------------------------------------------------------------
// bf16x2-split (3-product) tensor-core GEMM.  C[b](M x N) = op(A[b]) @ op(B[b])
//   TA=0: A row-major (M,K).  TA=1: A[m][k] = src[k*lda+m] (adj^T).
//   TB=0: B source (N,K) row-major.  TB=1: B[n][k] = src[k*ldb+n].
//   EPI: 0 store | 1 relu | 2 relu + C_old | 3 relu + Add
// CTA 128x128, BK=32, 256 thr; warp tile 32x64 (warp_m=wid&3, warp_n=wid>>2).
// ---------------------------------------------------------------------------
template<int TA, int TB, int EPI>
__global__ __launch_bounds__(256)
void tc_gemm(const float* __restrict__ A, long sA, int lda,
             const float* __restrict__ B, long sB, int ldb,
             float* __restrict__ C, long sC, int ldc,
             const float* __restrict__ Add, long sAdd, int K)
{
    extern __shared__ char smem[];
    const int tid = threadIdx.x, lane = tid & 31, wid = tid >> 5;
    const int b  = blockIdx.z;
    const int m0 = blockIdx.y * 128;
    const int n0 = blockIdx.x * 128;
    const float* Ab = A + (long)b * sA;
    const float* Bb = B + (long)b * sB;
    float*       Cb = C + (long)b * sC;

    const int am = (wid & 3) * 32;   // warp rows
    const int bn = (wid >> 2) * 64;  // warp cols

    float acc[2][8][4];
    #pragma unroll
    for (int i = 0; i < 2; i++)
        #pragma unroll
        for (int j = 0; j < 8; j++)
            #pragma unroll
            for (int e = 0; e < 4; e++) acc[i][j][e] = 0.f;

    const int nch = K >> 5;

    stage_tile<TA>(Ab, lda, 0, m0, smem,          smem + 8192,  tid);
    stage_tile<TB>(Bb, ldb, 0, n0, smem + 16384,  smem + 24576, tid);
    __syncthreads();

    for (int ch = 0; ch < nch; ch++) {
        const int d = ch & 1;
        char* cur = smem + d * STG;
        if (ch + 1 < nch) {
            char* nxt = smem + (d ^ 1) * STG;
            stage_tile<TA>(Ab, lda, (ch + 1) << 5, m0, nxt,         nxt + 8192,  tid);
            stage_tile<TB>(Bb, ldb, (ch + 1) << 5, n0, nxt + 16384, nxt + 24576, tid);
        }
        const uint32_t uAh = smem_u32(cur);
        const uint32_t uAl = uAh + 8192;
        const uint32_t uBh = uAh + 16384;
        const uint32_t uBl = uAh + 24576;

        #pragma unroll
        for (int ks = 0; ks < 2; ks++) {
            // ---- A fragments (2 m-tiles, hi+lo) ----
            uint32_t Ah[2][4], Al[2][4];
            #pragma unroll
            for (int mt = 0; mt < 2; mt++) {
                uint32_t off;
                if (!TA) {
                    uint32_t row = (uint32_t)(am + mt * 16 + (lane & 15));
                    uint32_t cb  = (uint32_t)(ks * 32 + ((lane >> 4) << 4));
                    off = off_rk(row, cb);
                } else {
                    uint32_t grp = lane >> 3, t8 = lane & 7;
                    uint32_t k   = (uint32_t)(ks * 16) + ((grp >> 1) << 3) + t8;
                    uint32_t cb  = (uint32_t)(am + mt * 16 + ((grp & 1) << 3)) * 2;
                    off = off_kn(k, cb);
                }
                if (!TA) {
                    ldsm4(Ah[mt][0], Ah[mt][1], Ah[mt][2], Ah[mt][3], uAh + off);
                    ldsm4(Al[mt][0], Al[mt][1], Al[mt][2], Al[mt][3], uAl + off);
                } else {
                    ldsm4t(Ah[mt][0], Ah[mt][1], Ah[mt][2], Ah[mt][3], uAh + off);
                    ldsm4t(Al[mt][0], Al[mt][1], Al[mt][2], Al[mt][3], uAl + off);
                }
            }
            // ---- B fragments (8 n-tiles as 4 x4 loads, hi+lo) ----
            uint32_t Bh[8][2], Bl[8][2];
            #pragma unroll
            for (int p = 0; p < 4; p++) {
                uint32_t off;
                if (!TB) {
                    uint32_t row = (uint32_t)(bn + p * 16 + (lane & 15));
                    uint32_t cb  = (uint32_t)(ks * 32 + ((lane >> 4) << 4));
                    off = off_rk(row, cb);
                } else {
                    uint32_t grp = lane >> 3, t8 = lane & 7;
                    uint32_t k   = (uint32_t)(ks * 16) + ((grp >> 1) << 3) + t8;
                    uint32_t cb  = (uint32_t)(bn + p * 16 + ((grp & 1) << 3)) * 2;
                    off = off_kn(k, cb);
                }
                uint32_t r0, r1, r2, r3;
                if (!TB) ldsm4 (r0, r1, r2, r3, uBh + off);
                else     ldsm4t(r0, r1, r2, r3, uBh + off);
                Bh[2*p][0] = r0; Bh[2*p][1] = r2; Bh[2*p+1][0] = r1; Bh[2*p+1][1] = r3;
                if (!TB) ldsm4 (r0, r1, r2, r3, uBl + off);
                else     ldsm4t(r0, r1, r2, r3, uBl + off);
                Bl[2*p][0] = r0; Bl[2*p][1] = r2; Bl[2*p+1][0] = r1; Bl[2*p+1][1] = r3;
            }
            // ---- 3-product MMAs, reordered for accumulator ILP:
            //      16 independent accumulators between reuses; per-accumulator
            //      order stays HH, HL, LH (numerics identical to R3). ----
            #pragma unroll
            for (int mt = 0; mt < 2; mt++)
                #pragma unroll
                for (int nt = 0; nt < 8; nt++) mma16816(acc[mt][nt], Ah[mt], Bh[nt]);
            #pragma unroll
            for (int mt = 0; mt < 2; mt++)
                #pragma unroll
                for (int nt = 0; nt < 8; nt++) mma16816(acc[mt][nt], Ah[mt], Bl[nt]);
            #pragma unroll
            for (int mt = 0; mt < 2; mt++)
                #pragma unroll
                for (int nt = 0; nt < 8; nt++) mma16816(acc[mt][nt], Al[mt], Bh[nt]);
        }
        __syncthreads();
    }

    // ---- epilogue ----
    #pragma unroll
    for (int mt = 0; mt < 2; mt++) {
        #pragma unroll
        for (int half = 0; half < 2; half++) {
            int row = m0 + am + mt * 16 + (lane >> 2) + half * 8;
            float* crow = Cb + (long)row * ldc + n0 + bn + (lane & 3) * 2;
            const float* arow = (EPI == 3)
                ? Add + (long)b * sAdd + (long)row * ldc + n0 + bn + (lane & 3) * 2 : nullptr;
            #pragma unroll
            for (int nt = 0; nt < 8; nt++) {
                float x = acc[mt][nt][half * 2 + 0];
                float y = acc[mt][nt][half * 2 + 1];
                if (EPI >= 1) { x = fmaxf(x, 0.f); y = fmaxf(y, 0.f); }
                if (EPI == 2) { float2 o = *(const float2*)&crow[nt * 8]; x += o.x; y += o.y; }
                if (EPI == 3) { float2 o = *(const float2*)&arow[nt * 8]; x += o.x; y += o.y; }
                float2 v; v.x = x; v.y = y;
                *(float2*)&crow[nt * 8] = v;
            }
        }
    }
}

// ---------------------------------------------------------------------------
// Row softmax over last dim (256), in place.
// ---------------------------------------------------------------------------
__global__ __launch_bounds__(256)
void softmax_kernel(float* __restrict__ S)
{
    __shared__ float sm[8];
    const long row = blockIdx.x;
    float* p = S + row * (long)NN;
    const int t = threadIdx.x;

    float v = p[t];
    float m = v;
    #pragma unroll
    for (int o = 16; o > 0; o >>= 1) m = fmaxf(m, __shfl_xor_sync(0xffffffffu, m, o));
    if ((t & 31) == 0) sm[t >> 5] = m;
    __syncthreads();
    m = sm[0];
    #pragma unroll
    for (int i = 1; i < 8; i++) m = fmaxf(m, sm[i]);

    float e = expf(v - m);
    float s = e;
    #pragma unroll
    for (int o = 16; o > 0; o >>= 1) s += __shfl_xor_sync(0xffffffffu, s, o);
    __syncthreads();
    if ((t & 31) == 0) sm[t >> 5] = s;
    __syncthreads();
    s = 0.f;
    #pragma unroll
    for (int i = 0; i < 8; i++) s += sm[i];

    p[t] = e / s;
}

// ---------------------------------------------------------------------------
extern "C" void kernel_launch(void* const* d_in, const int* in_sizes, int n_in,
                              void* d_out, int out_size)
{
    const float* f     = (const float*)d_in[0];
    const float* adj   = (const float*)d_in[2];
    const float* Wse1  = (const float*)d_in[3];
    const float* Wse2  = (const float*)d_in[4];
    const float* Wst1  = (const float*)d_in[5];
    const float* Wst2  = (const float*)d_in[6];
    const float* Wst3  = (const float*)d_in[7];
    const float* Wst1b = (const float*)d_in[8];
    const float* Wst2b = (const float*)d_in[9];
    const float* Wst3b = (const float*)d_in[10];
    const float* Wsim1 = (const float*)d_in[11];
    const float* Wsim2 = (const float*)d_in[12];
    const float* Wsim3 = (const float*)d_in[13];
    float* out = (float*)d_out;

    float *b1, *b2, *b3, *b4, *S;
    cudaGetSymbolAddress((void**)&b1, g_b1);
    cudaGetSymbolAddress((void**)&b2, g_b2);
    cudaGetSymbolAddress((void**)&b3, g_b3);
    cudaGetSymbolAddress((void**)&b4, g_b4);
    cudaGetSymbolAddress((void**)&S,  g_S);

    cudaFuncSetAttribute(tc_gemm<0,0,0>, cudaFuncAttributeMaxDynamicSharedMemorySize, SMEM_TOTAL);
    cudaFuncSetAttribute(tc_gemm<0,1,0>, cudaFuncAttributeMaxDynamicSharedMemorySize, SMEM_TOTAL);
    cudaFuncSetAttribute(tc_gemm<0,1,1>, cudaFuncAttributeMaxDynamicSharedMemorySize, SMEM_TOTAL);
    cudaFuncSetAttribute(tc_gemm<1,1,2>, cudaFuncAttributeMaxDynamicSharedMemorySize, SMEM_TOTAL);
    cudaFuncSetAttribute(tc_gemm<0,1,3>, cudaFuncAttributeMaxDynamicSharedMemorySize, SMEM_TOTAL);

    const dim3 blk(256);
    const dim3 g1(CC/128, NN/128, BSZ);   // (4,2,64): M=256, N=512
    const dim3 g3(NN/128, NN/128, BSZ);   // (2,2,64): M=256, N=256
    const int SM = SMEM_TOTAL;

    // similarity graph: S = softmax((f Wse1^T)(f Wse2^T)^T)
    tc_gemm<0,0,0><<<g1, blk, SM>>>(f, NC, CC, Wse1, 0, CC, b1, NC, CC, nullptr, 0, CC);
    tc_gemm<0,0,0><<<g1, blk, SM>>>(f, NC, CC, Wse2, 0, CC, b2, NC, CC, nullptr, 0, CC);
    tc_gemm<0,0,0><<<g3, blk, SM>>>(b1, NC, CC, b2, NC, CC, S, NNN, NN, nullptr, 0, CC);
    softmax_kernel<<<BSZ*NN, blk>>>(S);

    // st branch layer 1 -> b1
    tc_gemm<0,1,0><<<g1, blk, SM>>>(f, NC, CC, Wst1,  0, CC, b3, NC, CC, nullptr, 0, CC);
    tc_gemm<0,1,0><<<g1, blk, SM>>>(f, NC, CC, Wst1b, 0, CC, b4, NC, CC, nullptr, 0, CC);
    tc_gemm<0,1,1><<<g1, blk, SM>>>(adj, NNN, NN, b3, NC, CC, b1, NC, CC, nullptr, 0, NN);
    tc_gemm<1,1,2><<<g1, blk, SM>>>(adj, NNN, NN, b4, NC, CC, b1, NC, CC, nullptr, 0, NN);
    // layer 2 -> b2
    tc_gemm<0,1,0><<<g1, blk, SM>>>(b1, NC, CC, Wst2,  0, CC, b3, NC, CC, nullptr, 0, CC);
    tc_gemm<0,1,0><<<g1, blk, SM>>>(b1, NC, CC, Wst2b, 0, CC, b4, NC, CC, nullptr, 0, CC);
    tc_gemm<0,1,1><<<g1, blk, SM>>>(adj, NNN, NN, b3, NC, CC, b2, NC, CC, nullptr, 0, NN);
    tc_gemm<1,1,2><<<g1, blk, SM>>>(adj, NNN, NN, b4, NC, CC, b2, NC, CC, nullptr, 0, NN);
    // layer 3 -> b1
    tc_gemm<0,1,0><<<g1, blk, SM>>>(b2, NC, CC, Wst3,  0, CC, b3, NC, CC, nullptr, 0, CC);
    tc_gemm<0,1,0><<<g1, blk, SM>>>(b2, NC, CC, Wst3b, 0, CC, b4, NC, CC, nullptr, 0, CC);
    tc_gemm<0,1,1><<<g1, blk, SM>>>(adj, NNN, NN, b3, NC, CC, b1, NC, CC, nullptr, 0, NN);
    tc_gemm<1,1,2><<<g1, blk, SM>>>(adj, NNN, NN, b4, NC, CC, b1, NC, CC, nullptr, 0, NN);

    // sim branch
    tc_gemm<0,1,0><<<g1, blk, SM>>>(f, NC, CC, Wsim1, 0, CC, b3, NC, CC, nullptr, 0, CC);
    tc_gemm<0,1,1><<<g1, blk, SM>>>(S, NNN, NN, b3, NC, CC, b2, NC, CC, nullptr, 0, NN);
    tc_gemm<0,1,0><<<g1, blk, SM>>>(b2, NC, CC, Wsim2, 0, CC, b3, NC, CC, nullptr, 0, CC);
    tc_gemm<0,1,1><<<g1, blk, SM>>>(S, NNN, NN, b3, NC, CC, b4, NC, CC, nullptr, 0, NN);
    tc_gemm<0,1,0><<<g1, blk, SM>>>(b4, NC, CC, Wsim3, 0, CC, b3, NC, CC, nullptr, 0, CC);
    // out = relu(S @ Y3) + st
    tc_gemm<0,1,3><<<g1, blk, SM>>>(S, NNN, NN, b3, NC, CC, out, NC, CC, b1, NC, NN);
}